// round 16
// baseline (speedup 1.0000x reference)
#include <cuda_runtime.h>
#include <cuda_bf16.h>
#include <math.h>
#include <float.h>
#include <stdint.h>

// ---------------- problem constants -------------------------------
#define T_TOK 4096
#define C_SP  4096
#define HID   1024
#define METAF 20
#define SPAND 3092
#define UHID  1024
#define M_TOP 1024
#define K_ANT 50
#define NEGV  (-1e30f)
#define KPAD  3136
#define NKT   49            // KPAD/64 k-tiles

// ---------------- device scratch ----------------------------------
__device__ float g_logits[T_TOK];
__device__ float g_span_emb[(size_t)C_SP * SPAND];
__device__ float g_hid1[(size_t)C_SP * UHID];
__device__ float g_mention[C_SP];
__device__ int   g_topidx[M_TOP];
__device__ float g_topm[M_TOP];
__device__ float g_tmp[(size_t)M_TOP * SPAND];
__device__ float g_fast[(size_t)M_TOP * M_TOP];
// fragment-major bf16 split operands
__device__ __nv_bfloat16 g_sa0[(size_t)C_SP * KPAD];   // span_emb, A-frag-128
__device__ __nv_bfloat16 g_sa1[(size_t)C_SP * KPAD];
__device__ __nv_bfloat16 g_sa2[(size_t)C_SP * KPAD];
__device__ __nv_bfloat16 g_wb0[(size_t)UHID * KPAD];   // w_u1^T, B-frag-128
__device__ __nv_bfloat16 g_wb1[(size_t)UHID * KPAD];
__device__ __nv_bfloat16 g_fbx0[(size_t)KPAD * KPAD];  // w_fast^T, B-frag-64
__device__ __nv_bfloat16 g_fbx1[(size_t)KPAD * KPAD];
__device__ __nv_bfloat16 g_fbx2[(size_t)KPAD * KPAD];
__device__ __nv_bfloat16 g_ta0[(size_t)M_TOP * KPAD];  // top_emb, A-frag-128
__device__ __nv_bfloat16 g_ta1[(size_t)M_TOP * KPAD];
__device__ __nv_bfloat16 g_ta2[(size_t)M_TOP * KPAD];
__device__ __nv_bfloat16 g_taB0[(size_t)M_TOP * KPAD]; // top_emb, B-frag-64
__device__ __nv_bfloat16 g_taB1[(size_t)M_TOP * KPAD];
__device__ __nv_bfloat16 g_taB2[(size_t)M_TOP * KPAD];
__device__ __nv_bfloat16 g_tb0[(size_t)M_TOP * KPAD];  // tmp, A-frag-128
__device__ __nv_bfloat16 g_tb1[(size_t)M_TOP * KPAD];
__device__ __nv_bfloat16 g_tb2[(size_t)M_TOP * KPAD];

// ---------------- fragment-layout helpers -------------------------
__device__ __forceinline__ uint32_t a_word(int rloc, int k16, int kp) {
    int rr = rloc & 15;
    return (uint32_t)(k16 * 1024 + (rloc >> 4) * 128
                      + ((rr & 7) * 4 + (kp & 3)) * 4 + (rr >> 3) + 2 * (kp >> 2));
}
__device__ __forceinline__ void a_inv(int w, int& rloc, int& k16, int& kp) {
    k16 = w >> 10; int r = w & 1023;
    int matom = r >> 7; int r2 = r & 127;
    int lane = r2 >> 2, j = r2 & 3;
    int rr = (lane >> 2) + 8 * (j & 1);
    kp = (lane & 3) + 4 * (j >> 1);
    rloc = matom * 16 + rr;
}
template<int BN>
__device__ __forceinline__ void b_inv(int w, int& nloc, int& k16, int& kp) {
    if (BN == 128) { k16 = w >> 10; } else { k16 = w >> 9; }
    int r = w & (BN * 8 - 1);
    int natom = r >> 6; int r2 = r & 63;
    int lane = r2 >> 1, j = r2 & 1;
    kp = (lane & 3) + 4 * j;
    nloc = natom * 8 + (lane >> 2);
}

__device__ __forceinline__ uint32_t pack_bf(__nv_bfloat16 lo, __nv_bfloat16 hi) {
    return (uint32_t)__bfloat16_as_ushort(lo) | ((uint32_t)__bfloat16_as_ushort(hi) << 16);
}
__device__ __forceinline__ void split3(float x, __nv_bfloat16& o0,
                                       __nv_bfloat16& o1, __nv_bfloat16& o2) {
    __nv_bfloat16 b0 = __float2bfloat16(x);
    float r1 = __fsub_rn(x, __bfloat162float(b0));
    __nv_bfloat16 b1 = __float2bfloat16(r1);
    float r2 = __fsub_rn(r1, __bfloat162float(b1));
    o0 = b0; o1 = b1; o2 = __float2bfloat16(r2);
}

#define CP_ASYNC16(smaddr, gptr) \
    asm volatile("cp.async.cg.shared.global [%0], [%1], 16;\n" :: "r"(smaddr), "l"(gptr))
#define CP_COMMIT() asm volatile("cp.async.commit_group;\n" ::: "memory")
#define CP_WAIT0()  asm volatile("cp.async.wait_group 0;\n" ::: "memory")

__device__ __forceinline__ uint32_t sm_addr(const void* p) {
    return (uint32_t)__cvta_generic_to_shared(p);
}

// ---------------- fused pre-kernel: token logits + w_u1 split -----
__global__ void k_pre(const float* __restrict__ hs,
                      const float* __restrict__ w_attn,
                      const float* __restrict__ b_attn,
                      const float* __restrict__ w_u1) {
    extern __shared__ float ts[];     // split blocks: [64][132]
    const int tid = threadIdx.x;
    if (blockIdx.x < 512) {
        int warp = (blockIdx.x * 256 + tid) >> 5;
        int lane = tid & 31;
        const float* row = hs + (size_t)warp * HID;
        double acc = 0.0;
        #pragma unroll 8
        for (int i = lane; i < HID; i += 32) acc += (double)row[i] * (double)w_attn[i];
        #pragma unroll
        for (int o = 16; o; o >>= 1) acc += __shfl_xor_sync(0xffffffffu, acc, o);
        if (lane == 0) g_logits[warp] = (float)(acc + (double)b_attn[0]);
        return;
    }
    const int bi = blockIdx.x - 512;
    const int kt = bi % NKT, tn = bi / NKT;
    const int PAD = 132;
    for (int i = tid; i < 64 * 32; i += 256) {
        int kk = i >> 5, c4 = i & 31;
        int gk = kt * 64 + kk, gn = tn * 128 + c4 * 4;
        float4 v = make_float4(0.f, 0.f, 0.f, 0.f);
        if (gk < SPAND)
            v = *(const float4*)&w_u1[(size_t)gk * UHID + gn];
        float* d = &ts[kk * PAD + c4 * 4];
        d[0] = v.x; d[1] = v.y; d[2] = v.z; d[3] = v.w;
    }
    __syncthreads();
    size_t wb = (size_t)(tn * NKT + kt) * 4096;
    uint32_t* o0 = (uint32_t*)g_wb0;
    uint32_t* o1 = (uint32_t*)g_wb1;
    for (int w = tid; w < 4096; w += 256) {
        int nloc, k16, kp;
        b_inv<128>(w, nloc, k16, kp);
        int kk = k16 * 16 + kp * 2;
        float x0 = ts[kk * PAD + nloc], x1 = ts[(kk + 1) * PAD + nloc];
        __nv_bfloat16 a0 = __float2bfloat16(x0);
        __nv_bfloat16 a1 = __float2bfloat16(__fsub_rn(x0, __bfloat162float(a0)));
        __nv_bfloat16 b0 = __float2bfloat16(x1);
        __nv_bfloat16 b1 = __float2bfloat16(__fsub_rn(x1, __bfloat162float(b0)));
        o0[wb + w] = pack_bf(a0, b0);
        o1[wb + w] = pack_bf(a1, b1);
    }
}

// ---------------- kernel: span embeddings -------------------------
__global__ void k_span_emb(const float* __restrict__ hs,
                           const int* __restrict__ starts,
                           const int* __restrict__ widths,
                           const float* __restrict__ w_width) {
    int c = blockIdx.x;
    int s = starts[c], w = widths[c];
    int e = s + w, L = w + 1;
    __shared__ float p[32];
    int tid = threadIdx.x;
    if (tid < 32) {
        double lg = (tid < L) ? (double)g_logits[s + tid] : -1e300;
        double mx = lg;
        #pragma unroll
        for (int o = 16; o; o >>= 1) {
            double v = __shfl_xor_sync(0xffffffffu, mx, o);
            mx = fmax(mx, v);
        }
        double ex = (tid < L) ? exp(lg - mx) : 0.0;
        double sm = ex;
        #pragma unroll
        for (int o = 16; o; o >>= 1) sm += __shfl_xor_sync(0xffffffffu, sm, o);
        p[tid] = (float)(ex / sm);
    }
    __syncthreads();
    float* out = g_span_emb + (size_t)c * SPAND;
    const float* hrow_s = hs + (size_t)s * HID;
    const float* hrow_e = hs + (size_t)e * HID;
    for (int h = tid; h < HID; h += blockDim.x) {
        out[h]        = hrow_s[h];
        out[HID + h]  = hrow_e[h];
        float acc = 0.f, cmp = 0.f;
        for (int l = 0; l < L; ++l) {
            float y = __fmaf_rn(p[l], hs[(size_t)(s + l) * HID + h], -cmp);
            float t = __fadd_rn(acc, y);
            cmp = __fsub_rn(__fsub_rn(t, acc), y);
            acc = t;
        }
        out[2 * HID + METAF + h] = acc;
    }
    if (tid < METAF) out[2 * HID + tid] = w_width[w * METAF + tid];
}

// ---------------- split: row-major fp32 -> A-frag-128 -------------
__global__ void k_splitA_frag(const float* __restrict__ src,
                              __nv_bfloat16* __restrict__ D0,
                              __nv_bfloat16* __restrict__ D1,
                              __nv_bfloat16* __restrict__ D2) {
    extern __shared__ float ts[];     // [128][68]
    const int tid = threadIdx.x;
    const int kt = blockIdx.x, tm = blockIdx.y;
    for (int i = tid; i < 128 * 16; i += 256) {
        int r = i >> 4, c4 = i & 15;
        int k = kt * 64 + c4 * 4;
        float4 v = make_float4(0.f, 0.f, 0.f, 0.f);
        if (k < SPAND)
            v = *(const float4*)&src[(size_t)(tm * 128 + r) * SPAND + k];
        float* d = &ts[r * 68 + c4 * 4];
        d[0] = v.x; d[1] = v.y; d[2] = v.z; d[3] = v.w;
    }
    __syncthreads();
    size_t wb = (size_t)(tm * NKT + kt) * 4096;
    uint32_t* o0 = (uint32_t*)D0;
    uint32_t* o1 = (uint32_t*)D1;
    uint32_t* o2 = (uint32_t*)D2;
    for (int w = tid; w < 4096; w += 256) {
        int rloc, k16, kp;
        a_inv(w, rloc, k16, kp);
        int kk = k16 * 16 + kp * 2;
        float x0 = ts[rloc * 68 + kk], x1 = ts[rloc * 68 + kk + 1];
        __nv_bfloat16 a0, a1, a2, b0, b1, b2;
        split3(x0, a0, a1, a2);
        split3(x1, b0, b1, b2);
        o0[wb + w] = pack_bf(a0, b0);
        o1[wb + w] = pack_bf(a1, b1);
        if (D2) o2[wb + w] = pack_bf(a2, b2);
    }
}

// ---------------- split: w_fast[K,N] -> B-frag-64 x3 --------------
__global__ void k_splitB64(const float* __restrict__ W) {
    extern __shared__ float ts[];     // [64][68]
    const int PAD = 68;
    const int tid = threadIdx.x;
    const int kt = blockIdx.x, tn = blockIdx.y;
    for (int i = tid; i < 64 * 16; i += 256) {
        int kk = i >> 4, c4 = i & 15;
        int gk = kt * 64 + kk, gn = tn * 64 + c4 * 4;
        float4 v = make_float4(0.f, 0.f, 0.f, 0.f);
        if (gk < SPAND && gn < SPAND)
            v = *(const float4*)&W[(size_t)gk * SPAND + gn];
        float* d = &ts[kk * PAD + c4 * 4];
        d[0] = v.x; d[1] = v.y; d[2] = v.z; d[3] = v.w;
    }
    __syncthreads();
    size_t wb = (size_t)(tn * NKT + kt) * 2048;
    uint32_t* o0 = (uint32_t*)g_fbx0;
    uint32_t* o1 = (uint32_t*)g_fbx1;
    uint32_t* o2 = (uint32_t*)g_fbx2;
    for (int w = tid; w < 2048; w += 256) {
        int nloc, k16, kp;
        b_inv<64>(w, nloc, k16, kp);
        int kk = k16 * 16 + kp * 2;
        float x0 = ts[kk * PAD + nloc], x1 = ts[(kk + 1) * PAD + nloc];
        __nv_bfloat16 a0, a1, a2, b0, b1, b2;
        split3(x0, a0, a1, a2);
        split3(x1, b0, b1, b2);
        o0[wb + w] = pack_bf(a0, b0);
        o1[wb + w] = pack_bf(a1, b1);
        o2[wb + w] = pack_bf(a2, b2);
    }
}

// ---------------- gathers -----------------------------------------
__global__ void k_gatherA() {         // grid (NKT, 8)
    __shared__ int cidx[128];
    const int tid = threadIdx.x;
    const int kt = blockIdx.x, tm = blockIdx.y;
    if (tid < 128) cidx[tid] = g_topidx[tm * 128 + tid];
    __syncthreads();
    size_t wb = (size_t)(tm * NKT + kt) * 4096;
    for (int w = tid; w < 4096; w += 256) {
        int rloc, k16, kp;
        a_inv(w, rloc, k16, kp);
        int ci = cidx[rloc];
        size_t sw = (size_t)((ci >> 7) * NKT + kt) * 4096 + a_word(ci & 127, k16, kp);
        ((uint32_t*)g_ta0)[wb + w] = ((const uint32_t*)g_sa0)[sw];
        ((uint32_t*)g_ta1)[wb + w] = ((const uint32_t*)g_sa1)[sw];
        ((uint32_t*)g_ta2)[wb + w] = ((const uint32_t*)g_sa2)[sw];
    }
}
__global__ void k_gatherB() {         // grid (NKT, 16)
    __shared__ int cidx[64];
    const int tid = threadIdx.x;
    const int kt = blockIdx.x, tn = blockIdx.y;
    if (tid < 64) cidx[tid] = g_topidx[tn * 64 + tid];
    __syncthreads();
    size_t wb = (size_t)(tn * NKT + kt) * 2048;
    for (int w = tid; w < 2048; w += 256) {
        int nloc, k16, kp;
        b_inv<64>(w, nloc, k16, kp);
        int ci = cidx[nloc];
        size_t sw = (size_t)((ci >> 7) * NKT + kt) * 4096 + a_word(ci & 127, k16, kp);
        ((uint32_t*)g_taB0)[wb + w] = ((const uint32_t*)g_sa0)[sw];
        ((uint32_t*)g_taB1)[wb + w] = ((const uint32_t*)g_sa1)[sw];
        ((uint32_t*)g_taB2)[wb + w] = ((const uint32_t*)g_sa2)[sw];
    }
}
__global__ void k_topmeta(float* __restrict__ out_topidx) {
    int t = threadIdx.x;
    int ci = g_topidx[t];
    g_topm[t] = g_mention[ci];
    out_topidx[t] = (float)ci;
}

// ---------------- bf16 MMA ----------------------------------------
__device__ __forceinline__ void mma_bf16(float c[4], const uint4& a, const uint2& b) {
    asm volatile(
        "mma.sync.aligned.m16n8k16.row.col.f32.bf16.bf16.f32 "
        "{%0,%1,%2,%3}, {%4,%5,%6,%7}, {%8,%9}, {%0,%1,%2,%3};"
        : "+f"(c[0]), "+f"(c[1]), "+f"(c[2]), "+f"(c[3])
        : "r"(a.x), "r"(a.y), "r"(a.z), "r"(a.w), "r"(b.x), "r"(b.y));
}

// ---------------- GEMM3: bf16x2 3-pass, single-stage 2 CTA/SM -----
// Measured R14: tensor pipe 67%, 209us. Keep.
__global__ __launch_bounds__(256, 2)
void k_gemm3(const float* __restrict__ bias, float* __restrict__ C) {
    extern __shared__ char sm[];
    const int tid = threadIdx.x, lane = tid & 31, wid = tid >> 5;
    const int warp_m = wid >> 1, warp_n = wid & 1;
    const int tm = blockIdx.y, tn = blockIdx.x;
    const __nv_bfloat16* Ab[2] = {g_sa0, g_sa1};
    const __nv_bfloat16* Bb[2] = {g_wb0, g_wb1};

    float c[2][8][4];
    #pragma unroll
    for (int ma = 0; ma < 2; ++ma)
        #pragma unroll
        for (int nb = 0; nb < 8; ++nb)
            #pragma unroll
            for (int q = 0; q < 4; ++q) c[ma][nb][q] = 0.f;

    auto load_tile = [&](int kt) {
        for (int i = tid; i < 4096; i += 256) {
            int region = i >> 10, off = i & 1023;
            const char* src = (region < 2)
                ? (const char*)Ab[region] + ((size_t)(tm * NKT + kt)) * 16384 + (size_t)off * 16
                : (const char*)Bb[region - 2] + ((size_t)(tn * NKT + kt)) * 16384 + (size_t)off * 16;
            CP_ASYNC16(sm_addr(sm + region * 16384 + off * 16), src);
        }
        CP_COMMIT();
    };
    load_tile(0);

    for (int kt = 0; kt < NKT; ++kt) {
        CP_WAIT0();
        __syncthreads();
        char* bA = sm;
        char* bB = sm + 32768;
        #pragma unroll
        for (int k16 = 0; k16 < 4; ++k16) {
            uint4 a[2][2]; uint2 b[2][8];
            #pragma unroll
            for (int s = 0; s < 2; ++s)
                #pragma unroll
                for (int ma = 0; ma < 2; ++ma)
                    a[s][ma] = *(const uint4*)(bA + s * 16384 + k16 * 4096
                                               + (warp_m * 2 + ma) * 512 + lane * 16);
            #pragma unroll
            for (int s = 0; s < 2; ++s)
                #pragma unroll
                for (int nb = 0; nb < 8; ++nb)
                    b[s][nb] = *(const uint2*)(bB + s * 16384 + k16 * 4096
                                               + (warp_n * 8 + nb) * 256 + lane * 8);
            #pragma unroll
            for (int ma = 0; ma < 2; ++ma)
                #pragma unroll
                for (int nb = 0; nb < 8; ++nb) {
                    mma_bf16(c[ma][nb], a[0][ma], b[0][nb]);
                    mma_bf16(c[ma][nb], a[0][ma], b[1][nb]);
                    mma_bf16(c[ma][nb], a[1][ma], b[0][nb]);
                }
        }
        __syncthreads();
        if (kt + 1 < NKT) load_tile(kt + 1);
    }

    const int g = lane >> 2, t = lane & 3;
    const int row0 = tm * 128, col0 = tn * 128;
    #pragma unroll
    for (int ma = 0; ma < 2; ++ma) {
        int r0 = row0 + (warp_m * 2 + ma) * 16 + g;
        #pragma unroll
        for (int nb = 0; nb < 8; ++nb) {
            int cc = col0 + (warp_n * 8 + nb) * 8 + 2 * t;
            float b0 = bias[cc], b1 = bias[cc + 1];
            float v0 = fmaxf(__fadd_rn(c[ma][nb][0], b0), 0.f);
            float v1 = fmaxf(__fadd_rn(c[ma][nb][1], b1), 0.f);
            float v2 = fmaxf(__fadd_rn(c[ma][nb][2], b0), 0.f);
            float v3 = fmaxf(__fadd_rn(c[ma][nb][3], b1), 0.f);
            *(float2*)&C[(size_t)r0 * UHID + cc] = make_float2(v0, v1);
            *(float2*)&C[(size_t)(r0 + 8) * UHID + cc] = make_float2(v2, v3);
        }
    }
}

// ---------------- GEMM6: bf16x3 6-pass, no-Kahan, 2 CTA/SM --------
// R16: drop the Kahan compensation (cmp regs) to afford 2 CTAs/SM
// with A-fragments cached per k16. Error model: per-kt local partial
// (24 MMA folds) ~2.3e-6 + plain 49-fold chain ~1.4e-5 -> total
// ~2e-5, same class as the R5 config that passed at rel_err 1e-34.
__global__ __launch_bounds__(256, 2)
void k_gemm6(const __nv_bfloat16* __restrict__ A0, const __nv_bfloat16* __restrict__ A1,
             const __nv_bfloat16* __restrict__ A2,
             const __nv_bfloat16* __restrict__ B0, const __nv_bfloat16* __restrict__ B1,
             const __nv_bfloat16* __restrict__ B2,
             const float* __restrict__ bias, float* __restrict__ C,
             int Nstore, int ldc) {
    extern __shared__ char sm[];
    const int tid = threadIdx.x, lane = tid & 31, wid = tid >> 5;
    const int warp_m = wid >> 1, warp_n = wid & 1;
    const int tm = blockIdx.y, tn = blockIdx.x;
    const __nv_bfloat16* Ab[3] = {A0, A1, A2};
    const __nv_bfloat16* Bb[3] = {B0, B1, B2};

    float acc[2][4][4];
    #pragma unroll
    for (int ma = 0; ma < 2; ++ma)
        #pragma unroll
        for (int nb = 0; nb < 4; ++nb)
            #pragma unroll
            for (int q = 0; q < 4; ++q) acc[ma][nb][q] = 0.f;

    auto load_tile = [&](int kt) {
        for (int i = tid; i < 4608; i += 256) {
            const char* src; uint32_t doff;
            if (i < 3072) {
                int s = i >> 10, off = i & 1023;
                src = (const char*)Ab[s] + ((size_t)(tm * NKT + kt)) * 16384 + (size_t)off * 16;
                doff = s * 16384 + off * 16;
            } else {
                int j = i - 3072;
                int s = j >> 9, off = j & 511;
                src = (const char*)Bb[s] + ((size_t)(tn * NKT + kt)) * 8192 + (size_t)off * 16;
                doff = 49152 + s * 8192 + off * 16;
            }
            CP_ASYNC16(sm_addr(sm + doff), src);
        }
        CP_COMMIT();
    };
    load_tile(0);

    const int pa[6] = {0, 0, 1, 1, 0, 2};
    const int pb[6] = {0, 1, 0, 1, 2, 0};

    for (int kt = 0; kt < NKT; ++kt) {
        CP_WAIT0();
        __syncthreads();
        char* bA = sm;
        char* bB = sm + 49152;
        float loc[2][4][4];
        #pragma unroll
        for (int ma = 0; ma < 2; ++ma)
            #pragma unroll
            for (int nb = 0; nb < 4; ++nb)
                #pragma unroll
                for (int q = 0; q < 4; ++q) loc[ma][nb][q] = 0.f;
        #pragma unroll
        for (int k16 = 0; k16 < 4; ++k16) {
            // A-fragments: all 3 splits cached for this k16 (24 regs)
            uint4 a[3][2];
            #pragma unroll
            for (int s = 0; s < 3; ++s)
                #pragma unroll
                for (int ma = 0; ma < 2; ++ma)
                    a[s][ma] = *(const uint4*)(bA + s * 16384 + k16 * 4096
                                               + (warp_m * 2 + ma) * 512 + lane * 16);
            #pragma unroll
            for (int pr = 0; pr < 6; ++pr) {
                uint2 b[4];
                #pragma unroll
                for (int nb = 0; nb < 4; ++nb)
                    b[nb] = *(const uint2*)(bB + pb[pr] * 8192 + k16 * 2048
                                            + (warp_n * 4 + nb) * 256 + lane * 8);
                #pragma unroll
                for (int ma = 0; ma < 2; ++ma)
                    #pragma unroll
                    for (int nb = 0; nb < 4; ++nb)
                        mma_bf16(loc[ma][nb], a[pa[pr]][ma], b[nb]);
            }
        }
        // plain fold of k64 partial into master
        #pragma unroll
        for (int ma = 0; ma < 2; ++ma)
            #pragma unroll
            for (int nb = 0; nb < 4; ++nb)
                #pragma unroll
                for (int q = 0; q < 4; ++q)
                    acc[ma][nb][q] = __fadd_rn(acc[ma][nb][q], loc[ma][nb][q]);
        __syncthreads();
        if (kt + 1 < NKT) load_tile(kt + 1);
    }

    const int g = lane >> 2, t = lane & 3;
    const int row0 = tm * 128, col0 = tn * 64;
    #pragma unroll
    for (int ma = 0; ma < 2; ++ma) {
        int r0 = row0 + (warp_m * 2 + ma) * 16 + g;
        #pragma unroll
        for (int nb = 0; nb < 4; ++nb) {
            int cc = col0 + (warp_n * 4 + nb) * 8 + 2 * t;
            if (cc >= Nstore) continue;
            float v0 = acc[ma][nb][0], v1 = acc[ma][nb][1];
            float v2 = acc[ma][nb][2], v3 = acc[ma][nb][3];
            if (bias) {
                float b0 = bias[cc];
                float b1 = (cc + 1 < Nstore) ? bias[cc + 1] : 0.f;
                v0 = __fadd_rn(v0, b0); v1 = __fadd_rn(v1, b1);
                v2 = __fadd_rn(v2, b0); v3 = __fadd_rn(v3, b1);
            }
            if (cc + 1 < Nstore) {
                *(float2*)&C[(size_t)r0 * ldc + cc] = make_float2(v0, v1);
                *(float2*)&C[(size_t)(r0 + 8) * ldc + cc] = make_float2(v2, v3);
            } else {
                C[(size_t)r0 * ldc + cc] = v0;
                C[(size_t)(r0 + 8) * ldc + cc] = v2;
            }
        }
    }
}

// ---------------- mention score -----------------------------------
__global__ void k_score(const float* __restrict__ w_u2,
                        const float* __restrict__ b_u2) {
    int warp = (blockIdx.x * blockDim.x + threadIdx.x) >> 5;
    int lane = threadIdx.x & 31;
    if (warp >= C_SP) return;
    const float* row = g_hid1 + (size_t)warp * UHID;
    double acc = 0.0;
    #pragma unroll 8
    for (int i = lane; i < UHID; i += 32) acc += (double)row[i] * (double)w_u2[i];
    #pragma unroll
    for (int o = 16; o; o >>= 1) acc += __shfl_xor_sync(0xffffffffu, acc, o);
    if (lane == 0) g_mention[warp] = (float)(acc + (double)b_u2[0]);
}

// ---------------- sort + greedy + compact -------------------------
__device__ __forceinline__ bool sort_before(float xk, int xi, float yk, int yi) {
    return (xk > yk) || (xk == yk && xi < yi);
}

__global__ void k_extract(const int* __restrict__ starts,
                          const int* __restrict__ widths) {
    extern __shared__ int sh[];
    float* key = (float*)sh;
    int* idx = sh + 4096;
    int* es  = sh + 8192;
    int* flg = sh + 12288;
    const int tid = threadIdx.x;       // 1024 threads
    const int ln32 = tid & 31, wrp = tid >> 5;
    const int ebase = wrp * 128 + ln32 * 4;

    for (int i = tid; i < C_SP; i += 1024) flg[i] = 0;

    float kq[4]; int iq[4];
    #pragma unroll
    for (int q = 0; q < 4; ++q) { kq[q] = g_mention[ebase + q]; iq[q] = ebase + q; }

    auto reg_phase = [&](unsigned k, unsigned j) {
        if (j >= 4) {
            unsigned lm = j >> 2;
            #pragma unroll
            for (int q = 0; q < 4; ++q) {
                float pk = __shfl_xor_sync(0xffffffffu, kq[q], lm);
                int   pi = __shfl_xor_sync(0xffffffffu, iq[q], lm);
                int e = ebase + q;
                int i = e & ~(int)j;
                bool dir = ((i & (int)k) == 0);
                bool swp;
                if ((e & (int)j) == 0)
                    swp = (sort_before(pk, pi, kq[q], iq[q]) == dir);
                else
                    swp = (sort_before(kq[q], iq[q], pk, pi) == dir);
                if (swp) { kq[q] = pk; iq[q] = pi; }
            }
        } else if (j == 2) {
            #pragma unroll
            for (int q = 0; q < 2; ++q) {
                int i = ebase + q;
                bool dir = ((i & (int)k) == 0);
                if (sort_before(kq[q + 2], iq[q + 2], kq[q], iq[q]) == dir) {
                    float tk = kq[q]; int ti = iq[q];
                    kq[q] = kq[q + 2]; iq[q] = iq[q + 2];
                    kq[q + 2] = tk; iq[q + 2] = ti;
                }
            }
        } else {
            #pragma unroll
            for (int q = 0; q < 4; q += 2) {
                int i = ebase + q;
                bool dir = ((i & (int)k) == 0);
                if (sort_before(kq[q + 1], iq[q + 1], kq[q], iq[q]) == dir) {
                    float tk = kq[q]; int ti = iq[q];
                    kq[q] = kq[q + 1]; iq[q] = iq[q + 1];
                    kq[q + 1] = tk; iq[q + 1] = ti;
                }
            }
        }
    };

    for (unsigned k = 2; k <= 128; k <<= 1)
        for (unsigned j = k >> 1; j > 0; j >>= 1) reg_phase(k, j);
    #pragma unroll
    for (int q = 0; q < 4; ++q) { key[ebase + q] = kq[q]; idx[ebase + q] = iq[q]; }
    __syncthreads();

    for (unsigned k = 256; k <= 4096; k <<= 1) {
        for (unsigned j = k >> 1; j >= 128; j >>= 1) {
            for (unsigned t = tid; t < 2048; t += 1024) {
                unsigned i = ((t & ~(j - 1)) << 1) | (t & (j - 1));
                unsigned l = i | j;
                float ki = key[i], kl = key[l];
                int   ii = idx[i], il = idx[l];
                bool before_l_i = (kl > ki) || (kl == ki && il < ii);
                bool dir = ((i & k) == 0);
                if (before_l_i == dir) {
                    key[i] = kl; key[l] = ki;
                    idx[i] = il; idx[l] = ii;
                }
            }
            __syncthreads();
        }
        #pragma unroll
        for (int q = 0; q < 4; ++q) { kq[q] = key[ebase + q]; iq[q] = idx[ebase + q]; }
        for (unsigned j = 64; j > 0; j >>= 1) reg_phase(k, j);
        #pragma unroll
        for (int q = 0; q < 4; ++q) { key[ebase + q] = kq[q]; idx[ebase + q] = iq[q]; }
        __syncthreads();
    }

    volatile int* le = (volatile int*)key;
    volatile int* ves = (volatile int*)es;
    for (int i = tid; i < T_TOK; i += 1024) {
        ((int*)key)[i] = -1;
        es[i] = T_TOK;
    }
    __syncthreads();

    if (tid < 32) {
        int lane = tid;
        int count = 0;
        for (int p = 0; p < C_SP && count < M_TOP; ++p) {
            int ci = idx[p];
            int s = starts[ci];
            int w = widths[ci];
            int e = s + w;
            bool crossing = false;
            if (lane < w) {
                crossing = (le[s + 1 + lane] > e) | (ves[s + lane] < s);
            }
            unsigned m = __ballot_sync(0xffffffffu, crossing);
            if (m == 0u) {
                if (lane == 0) {
                    int cur = le[s]; if (e > cur) ((int*)key)[s] = e;
                    int cur2 = ves[e]; if (s < cur2) es[e] = s;
                    flg[ci] = 1;
                }
                count++;
            }
            __syncwarp();
        }
    }
    __syncthreads();

    __shared__ int wsum[32];
    __shared__ int woff[33];
    int base = tid * 4;
    int f0 = flg[base], f1 = flg[base + 1], f2 = flg[base + 2], f3 = flg[base + 3];
    int c = f0 + f1 + f2 + f3;
    int inc = c;
    int lane = tid & 31, wid = tid >> 5;
    #pragma unroll
    for (int o = 1; o < 32; o <<= 1) {
        int n = __shfl_up_sync(0xffffffffu, inc, o);
        if (lane >= o) inc += n;
    }
    if (lane == 31) wsum[wid] = inc;
    __syncthreads();
    if (tid == 0) {
        int run = 0;
        for (int i = 0; i < 32; ++i) { woff[i] = run; run += wsum[i]; }
        woff[32] = run;
    }
    __syncthreads();
    int pos = woff[wid] + (inc - c);
    if (f0) { if (pos < M_TOP) g_topidx[pos] = base;     pos++; }
    if (f1) { if (pos < M_TOP) g_topidx[pos] = base + 1; pos++; }
    if (f2) { if (pos < M_TOP) g_topidx[pos] = base + 2; pos++; }
    if (f3) { if (pos < M_TOP) g_topidx[pos] = base + 3; pos++; }
    int total = woff[32];
    for (int p = total + tid; p < M_TOP; p += 1024) g_topidx[p] = C_SP - 1;
}

// ---------------- fast scores + per-row top-50 --------------------
__global__ void k_topk(float* __restrict__ out_ant,
                       float* __restrict__ out_mask,
                       float* __restrict__ out_score) {
    __shared__ float v[M_TOP];
    __shared__ float wv[8];
    __shared__ int   wi[8];
    const int i = blockIdx.x;
    const int tid = threadIdx.x;
    const int lane = tid & 31, wid = tid >> 5;
    const float mi = g_topm[i];
    for (int j = tid; j < M_TOP; j += 256) {
        float val = __fadd_rn(__fadd_rn(__fadd_rn(mi, g_topm[j]),
                                        (j < i) ? 0.f : NEGV),
                              g_fast[(size_t)i * M_TOP + j]);
        v[j] = val;
    }
    __syncthreads();
    for (int k = 0; k < K_ANT; ++k) {
        float bv = -INFINITY; int bi = M_TOP;
        for (int j = tid; j < M_TOP; j += 256) {
            float x = v[j];
            if (x > bv || (x == bv && j < bi)) { bv = x; bi = j; }
        }
        #pragma unroll
        for (int o = 16; o; o >>= 1) {
            float ok = __shfl_xor_sync(0xffffffffu, bv, o);
            int   oi = __shfl_xor_sync(0xffffffffu, bi, o);
            if (ok > bv || (ok == bv && oi < bi)) { bv = ok; bi = oi; }
        }
        if (lane == 0) { wv[wid] = bv; wi[wid] = bi; }
        __syncthreads();
        if (tid == 0) {
            float fv = wv[0]; int fi = wi[0];
            #pragma unroll
            for (int w = 1; w < 8; ++w)
                if (wv[w] > fv || (wv[w] == fv && wi[w] < fi)) { fv = wv[w]; fi = wi[w]; }
            out_ant[(size_t)i * K_ANT + k]   = (float)fi;
            out_mask[(size_t)i * K_ANT + k]  = (fi < i) ? 1.f : 0.f;
            out_score[(size_t)i * K_ANT + k] = fv;
            v[fi] = -INFINITY;
        }
        __syncthreads();
    }
}

// ---------------- launch ------------------------------------------
extern "C" void kernel_launch(void* const* d_in, const int* in_sizes, int n_in,
                              void* d_out, int out_size) {
    const float* hs      = (const float*)d_in[0];
    const int*   starts  = (const int*)d_in[1];
    const int*   widths  = (const int*)d_in[2];
    int base = 3;
    if (n_in >= 14 && in_sizes[3] == 1 && in_sizes[4] == 1) base = 5;
    const float* w_width = (const float*)d_in[base + 0];
    const float* w_attn  = (const float*)d_in[base + 1];
    const float* b_attn  = (const float*)d_in[base + 2];
    const float* w_u1    = (const float*)d_in[base + 3];
    const float* b_u1    = (const float*)d_in[base + 4];
    const float* w_u2    = (const float*)d_in[base + 5];
    const float* b_u2    = (const float*)d_in[base + 6];
    const float* w_fast  = (const float*)d_in[base + 7];
    const float* b_fast  = (const float*)d_in[base + 8];

    float* out = (float*)d_out;
    float* out_topidx = out;
    float* out_ant    = out + M_TOP;
    float* out_mask   = out + M_TOP + M_TOP * K_ANT;
    float* out_score  = out + M_TOP + 2 * M_TOP * K_ANT;

    float *p_span, *p_hid1, *p_tmp, *p_fast;
    __nv_bfloat16 *p_sa0, *p_sa1, *p_sa2;
    __nv_bfloat16 *p_fb0, *p_fb1, *p_fb2;
    __nv_bfloat16 *p_ta0, *p_ta1, *p_ta2, *p_taB0, *p_taB1, *p_taB2;
    __nv_bfloat16 *p_tb0, *p_tb1, *p_tb2;
    cudaGetSymbolAddress((void**)&p_span, g_span_emb);
    cudaGetSymbolAddress((void**)&p_hid1, g_hid1);
    cudaGetSymbolAddress((void**)&p_tmp,  g_tmp);
    cudaGetSymbolAddress((void**)&p_fast, g_fast);
    cudaGetSymbolAddress((void**)&p_sa0, g_sa0);
    cudaGetSymbolAddress((void**)&p_sa1, g_sa1);
    cudaGetSymbolAddress((void**)&p_sa2, g_sa2);
    cudaGetSymbolAddress((void**)&p_fb0, g_fbx0);
    cudaGetSymbolAddress((void**)&p_fb1, g_fbx1);
    cudaGetSymbolAddress((void**)&p_fb2, g_fbx2);
    cudaGetSymbolAddress((void**)&p_ta0, g_ta0);
    cudaGetSymbolAddress((void**)&p_ta1, g_ta1);
    cudaGetSymbolAddress((void**)&p_ta2, g_ta2);
    cudaGetSymbolAddress((void**)&p_taB0, g_taB0);
    cudaGetSymbolAddress((void**)&p_taB1, g_taB1);
    cudaGetSymbolAddress((void**)&p_taB2, g_taB2);
    cudaGetSymbolAddress((void**)&p_tb0, g_tb0);
    cudaGetSymbolAddress((void**)&p_tb1, g_tb1);
    cudaGetSymbolAddress((void**)&p_tb2, g_tb2);

    cudaFuncSetAttribute(k_gemm3, cudaFuncAttributeMaxDynamicSharedMemorySize, 65536);
    cudaFuncSetAttribute(k_gemm6, cudaFuncAttributeMaxDynamicSharedMemorySize, 73728);
    cudaFuncSetAttribute(k_extract, cudaFuncAttributeMaxDynamicSharedMemorySize, 65536);

    const int smPre  = 64 * 132 * 4;     // k_pre split part
    const int smA    = 128 * 68 * 4;     // k_splitA_frag
    const int smB64  = 64 * 68 * 4;      // k_splitB64

    // #0: fused token_logits + w_u1 split
    k_pre<<<512 + NKT * 8, 256, smPre>>>(hs, w_attn, b_attn, w_u1);
    // #1: span embeddings
    k_span_emb<<<C_SP, 256>>>(hs, starts, widths, w_width);
    // #2: span_emb -> A-frag splits
    { dim3 g(NKT, C_SP / 128);
      k_splitA_frag<<<g, 256, smA>>>(p_span, p_sa0, p_sa1, p_sa2); }
    // #3: GEMM3
    { dim3 g(UHID / 128, C_SP / 128);
      k_gemm3<<<g, 256, 65536>>>(b_u1, p_hid1); }
    // w_fast split (needed only by GEMM7)
    { dim3 g(NKT, NKT); k_splitB64<<<g, 256, smB64>>>(w_fast); }
    k_score<<<C_SP * 32 / 256, 256>>>(w_u2, b_u2);
    k_extract<<<1, 1024, 65536>>>(starts, widths);
    k_topmeta<<<1, 1024>>>(out_topidx);
    { dim3 g(NKT, 8);  k_gatherA<<<g, 256>>>(); }
    { dim3 g(NKT, 16); k_gatherB<<<g, 256>>>(); }
    { dim3 g(NKT, M_TOP / 128);
      k_gemm6<<<g, 256, 73728>>>(p_ta0, p_ta1, p_ta2, p_fb0, p_fb1, p_fb2,
                                 b_fast, p_tmp, SPAND, SPAND); }
    { dim3 g(NKT, M_TOP / 128);
      k_splitA_frag<<<g, 256, smA>>>(p_tmp, p_tb0, p_tb1, p_tb2); }
    { dim3 g(M_TOP / 64, M_TOP / 128);
      k_gemm6<<<g, 256, 73728>>>(p_tb0, p_tb1, p_tb2, p_taB0, p_taB1, p_taB2,
                                 nullptr, p_fast, M_TOP, M_TOP); }
    k_topk<<<M_TOP, 256>>>(out_ant, out_mask, out_score);

    (void)in_sizes; (void)n_in; (void)out_size;
}

// round 17
// speedup vs baseline: 1.0739x; 1.0739x over previous
#include <cuda_runtime.h>
#include <cuda_bf16.h>
#include <math.h>
#include <float.h>
#include <stdint.h>

// ---------------- problem constants -------------------------------
#define T_TOK 4096
#define C_SP  4096
#define HID   1024
#define METAF 20
#define SPAND 3092
#define UHID  1024
#define M_TOP 1024
#define K_ANT 50
#define NEGV  (-1e30f)
#define KPAD  3136
#define NKT   49            // KPAD/64 k-tiles

// ---------------- device scratch ----------------------------------
__device__ float g_logits[T_TOK];
__device__ float g_span_emb[(size_t)C_SP * SPAND];
__device__ float g_hid1[(size_t)C_SP * UHID];
__device__ float g_mention[C_SP];
__device__ int   g_topidx[M_TOP];
__device__ float g_topm[M_TOP];
__device__ float g_tmp[(size_t)M_TOP * SPAND];
__device__ float g_fast[(size_t)M_TOP * M_TOP];
// fragment-major bf16 split operands
__device__ __nv_bfloat16 g_sa0[(size_t)C_SP * KPAD];   // span_emb, A-frag-128
__device__ __nv_bfloat16 g_sa1[(size_t)C_SP * KPAD];
__device__ __nv_bfloat16 g_sa2[(size_t)C_SP * KPAD];
__device__ __nv_bfloat16 g_wb0[(size_t)UHID * KPAD];   // w_u1^T, B-frag-128
__device__ __nv_bfloat16 g_wb1[(size_t)UHID * KPAD];
__device__ __nv_bfloat16 g_fbx0[(size_t)KPAD * KPAD];  // w_fast^T, B-frag-64
__device__ __nv_bfloat16 g_fbx1[(size_t)KPAD * KPAD];
__device__ __nv_bfloat16 g_fbx2[(size_t)KPAD * KPAD];
__device__ __nv_bfloat16 g_ta0[(size_t)M_TOP * KPAD];  // top_emb, A-frag-128
__device__ __nv_bfloat16 g_ta1[(size_t)M_TOP * KPAD];
__device__ __nv_bfloat16 g_ta2[(size_t)M_TOP * KPAD];
__device__ __nv_bfloat16 g_taB0[(size_t)M_TOP * KPAD]; // top_emb, B-frag-64
__device__ __nv_bfloat16 g_taB1[(size_t)M_TOP * KPAD];
__device__ __nv_bfloat16 g_taB2[(size_t)M_TOP * KPAD];
__device__ __nv_bfloat16 g_tb0[(size_t)M_TOP * KPAD];  // tmp, A-frag-128
__device__ __nv_bfloat16 g_tb1[(size_t)M_TOP * KPAD];
__device__ __nv_bfloat16 g_tb2[(size_t)M_TOP * KPAD];

// ---------------- fragment-layout helpers -------------------------
__device__ __forceinline__ uint32_t a_word(int rloc, int k16, int kp) {
    int rr = rloc & 15;
    return (uint32_t)(k16 * 1024 + (rloc >> 4) * 128
                      + ((rr & 7) * 4 + (kp & 3)) * 4 + (rr >> 3) + 2 * (kp >> 2));
}
__device__ __forceinline__ void a_inv(int w, int& rloc, int& k16, int& kp) {
    k16 = w >> 10; int r = w & 1023;
    int matom = r >> 7; int r2 = r & 127;
    int lane = r2 >> 2, j = r2 & 3;
    int rr = (lane >> 2) + 8 * (j & 1);
    kp = (lane & 3) + 4 * (j >> 1);
    rloc = matom * 16 + rr;
}
template<int BN>
__device__ __forceinline__ void b_inv(int w, int& nloc, int& k16, int& kp) {
    if (BN == 128) { k16 = w >> 10; } else { k16 = w >> 9; }
    int r = w & (BN * 8 - 1);
    int natom = r >> 6; int r2 = r & 63;
    int lane = r2 >> 1, j = r2 & 1;
    kp = (lane & 3) + 4 * j;
    nloc = natom * 8 + (lane >> 2);
}

__device__ __forceinline__ uint32_t pack_bf(__nv_bfloat16 lo, __nv_bfloat16 hi) {
    return (uint32_t)__bfloat16_as_ushort(lo) | ((uint32_t)__bfloat16_as_ushort(hi) << 16);
}
__device__ __forceinline__ void split3(float x, __nv_bfloat16& o0,
                                       __nv_bfloat16& o1, __nv_bfloat16& o2) {
    __nv_bfloat16 b0 = __float2bfloat16(x);
    float r1 = __fsub_rn(x, __bfloat162float(b0));
    __nv_bfloat16 b1 = __float2bfloat16(r1);
    float r2 = __fsub_rn(r1, __bfloat162float(b1));
    o0 = b0; o1 = b1; o2 = __float2bfloat16(r2);
}

#define CP_ASYNC16(smaddr, gptr) \
    asm volatile("cp.async.cg.shared.global [%0], [%1], 16;\n" :: "r"(smaddr), "l"(gptr))
#define CP_COMMIT() asm volatile("cp.async.commit_group;\n" ::: "memory")
#define CP_WAIT1()  asm volatile("cp.async.wait_group 1;\n" ::: "memory")
#define CP_WAIT0()  asm volatile("cp.async.wait_group 0;\n" ::: "memory")

__device__ __forceinline__ uint32_t sm_addr(const void* p) {
    return (uint32_t)__cvta_generic_to_shared(p);
}

// ---------------- fused pre-kernel: token logits + w_u1 split -----
__global__ void k_pre(const float* __restrict__ hs,
                      const float* __restrict__ w_attn,
                      const float* __restrict__ b_attn,
                      const float* __restrict__ w_u1) {
    extern __shared__ float ts[];     // split blocks: [64][132]
    const int tid = threadIdx.x;
    if (blockIdx.x < 512) {
        int warp = (blockIdx.x * 256 + tid) >> 5;
        int lane = tid & 31;
        const float* row = hs + (size_t)warp * HID;
        double acc = 0.0;
        #pragma unroll 8
        for (int i = lane; i < HID; i += 32) acc += (double)row[i] * (double)w_attn[i];
        #pragma unroll
        for (int o = 16; o; o >>= 1) acc += __shfl_xor_sync(0xffffffffu, acc, o);
        if (lane == 0) g_logits[warp] = (float)(acc + (double)b_attn[0]);
        return;
    }
    const int bi = blockIdx.x - 512;
    const int kt = bi % NKT, tn = bi / NKT;
    const int PAD = 132;
    for (int i = tid; i < 64 * 32; i += 256) {
        int kk = i >> 5, c4 = i & 31;
        int gk = kt * 64 + kk, gn = tn * 128 + c4 * 4;
        float4 v = make_float4(0.f, 0.f, 0.f, 0.f);
        if (gk < SPAND)
            v = *(const float4*)&w_u1[(size_t)gk * UHID + gn];
        float* d = &ts[kk * PAD + c4 * 4];
        d[0] = v.x; d[1] = v.y; d[2] = v.z; d[3] = v.w;
    }
    __syncthreads();
    size_t wb = (size_t)(tn * NKT + kt) * 4096;
    uint32_t* o0 = (uint32_t*)g_wb0;
    uint32_t* o1 = (uint32_t*)g_wb1;
    for (int w = tid; w < 4096; w += 256) {
        int nloc, k16, kp;
        b_inv<128>(w, nloc, k16, kp);
        int kk = k16 * 16 + kp * 2;
        float x0 = ts[kk * PAD + nloc], x1 = ts[(kk + 1) * PAD + nloc];
        __nv_bfloat16 a0 = __float2bfloat16(x0);
        __nv_bfloat16 a1 = __float2bfloat16(__fsub_rn(x0, __bfloat162float(a0)));
        __nv_bfloat16 b0 = __float2bfloat16(x1);
        __nv_bfloat16 b1 = __float2bfloat16(__fsub_rn(x1, __bfloat162float(b0)));
        o0[wb + w] = pack_bf(a0, b0);
        o1[wb + w] = pack_bf(a1, b1);
    }
}

// ---------------- kernel: span embeddings -------------------------
__global__ void k_span_emb(const float* __restrict__ hs,
                           const int* __restrict__ starts,
                           const int* __restrict__ widths,
                           const float* __restrict__ w_width) {
    int c = blockIdx.x;
    int s = starts[c], w = widths[c];
    int e = s + w, L = w + 1;
    __shared__ float p[32];
    int tid = threadIdx.x;
    if (tid < 32) {
        double lg = (tid < L) ? (double)g_logits[s + tid] : -1e300;
        double mx = lg;
        #pragma unroll
        for (int o = 16; o; o >>= 1) {
            double v = __shfl_xor_sync(0xffffffffu, mx, o);
            mx = fmax(mx, v);
        }
        double ex = (tid < L) ? exp(lg - mx) : 0.0;
        double sm = ex;
        #pragma unroll
        for (int o = 16; o; o >>= 1) sm += __shfl_xor_sync(0xffffffffu, sm, o);
        p[tid] = (float)(ex / sm);
    }
    __syncthreads();
    float* out = g_span_emb + (size_t)c * SPAND;
    const float* hrow_s = hs + (size_t)s * HID;
    const float* hrow_e = hs + (size_t)e * HID;
    for (int h = tid; h < HID; h += blockDim.x) {
        out[h]        = hrow_s[h];
        out[HID + h]  = hrow_e[h];
        float acc = 0.f, cmp = 0.f;
        for (int l = 0; l < L; ++l) {
            float y = __fmaf_rn(p[l], hs[(size_t)(s + l) * HID + h], -cmp);
            float t = __fadd_rn(acc, y);
            cmp = __fsub_rn(__fsub_rn(t, acc), y);
            acc = t;
        }
        out[2 * HID + METAF + h] = acc;
    }
    if (tid < METAF) out[2 * HID + tid] = w_width[w * METAF + tid];
}

// ---------------- split: row-major fp32 -> A-frag-128 -------------
__global__ void k_splitA_frag(const float* __restrict__ src,
                              __nv_bfloat16* __restrict__ D0,
                              __nv_bfloat16* __restrict__ D1,
                              __nv_bfloat16* __restrict__ D2) {
    extern __shared__ float ts[];     // [128][68]
    const int tid = threadIdx.x;
    const int kt = blockIdx.x, tm = blockIdx.y;
    for (int i = tid; i < 128 * 16; i += 256) {
        int r = i >> 4, c4 = i & 15;
        int k = kt * 64 + c4 * 4;
        float4 v = make_float4(0.f, 0.f, 0.f, 0.f);
        if (k < SPAND)
            v = *(const float4*)&src[(size_t)(tm * 128 + r) * SPAND + k];
        float* d = &ts[r * 68 + c4 * 4];
        d[0] = v.x; d[1] = v.y; d[2] = v.z; d[3] = v.w;
    }
    __syncthreads();
    size_t wb = (size_t)(tm * NKT + kt) * 4096;
    uint32_t* o0 = (uint32_t*)D0;
    uint32_t* o1 = (uint32_t*)D1;
    uint32_t* o2 = (uint32_t*)D2;
    for (int w = tid; w < 4096; w += 256) {
        int rloc, k16, kp;
        a_inv(w, rloc, k16, kp);
        int kk = k16 * 16 + kp * 2;
        float x0 = ts[rloc * 68 + kk], x1 = ts[rloc * 68 + kk + 1];
        __nv_bfloat16 a0, a1, a2, b0, b1, b2;
        split3(x0, a0, a1, a2);
        split3(x1, b0, b1, b2);
        o0[wb + w] = pack_bf(a0, b0);
        o1[wb + w] = pack_bf(a1, b1);
        if (D2) o2[wb + w] = pack_bf(a2, b2);
    }
}

// ---------------- split: w_fast[K,N] -> B-frag-64 x3 --------------
__global__ void k_splitB64(const float* __restrict__ W) {
    extern __shared__ float ts[];     // [64][68]
    const int PAD = 68;
    const int tid = threadIdx.x;
    const int kt = blockIdx.x, tn = blockIdx.y;
    for (int i = tid; i < 64 * 16; i += 256) {
        int kk = i >> 4, c4 = i & 15;
        int gk = kt * 64 + kk, gn = tn * 64 + c4 * 4;
        float4 v = make_float4(0.f, 0.f, 0.f, 0.f);
        if (gk < SPAND && gn < SPAND)
            v = *(const float4*)&W[(size_t)gk * SPAND + gn];
        float* d = &ts[kk * PAD + c4 * 4];
        d[0] = v.x; d[1] = v.y; d[2] = v.z; d[3] = v.w;
    }
    __syncthreads();
    size_t wb = (size_t)(tn * NKT + kt) * 2048;
    uint32_t* o0 = (uint32_t*)g_fbx0;
    uint32_t* o1 = (uint32_t*)g_fbx1;
    uint32_t* o2 = (uint32_t*)g_fbx2;
    for (int w = tid; w < 2048; w += 256) {
        int nloc, k16, kp;
        b_inv<64>(w, nloc, k16, kp);
        int kk = k16 * 16 + kp * 2;
        float x0 = ts[kk * PAD + nloc], x1 = ts[(kk + 1) * PAD + nloc];
        __nv_bfloat16 a0, a1, a2, b0, b1, b2;
        split3(x0, a0, a1, a2);
        split3(x1, b0, b1, b2);
        o0[wb + w] = pack_bf(a0, b0);
        o1[wb + w] = pack_bf(a1, b1);
        o2[wb + w] = pack_bf(a2, b2);
    }
}

// ---------------- gathers -----------------------------------------
__global__ void k_gatherA() {         // grid (NKT, 8)
    __shared__ int cidx[128];
    const int tid = threadIdx.x;
    const int kt = blockIdx.x, tm = blockIdx.y;
    if (tid < 128) cidx[tid] = g_topidx[tm * 128 + tid];
    __syncthreads();
    size_t wb = (size_t)(tm * NKT + kt) * 4096;
    for (int w = tid; w < 4096; w += 256) {
        int rloc, k16, kp;
        a_inv(w, rloc, k16, kp);
        int ci = cidx[rloc];
        size_t sw = (size_t)((ci >> 7) * NKT + kt) * 4096 + a_word(ci & 127, k16, kp);
        ((uint32_t*)g_ta0)[wb + w] = ((const uint32_t*)g_sa0)[sw];
        ((uint32_t*)g_ta1)[wb + w] = ((const uint32_t*)g_sa1)[sw];
        ((uint32_t*)g_ta2)[wb + w] = ((const uint32_t*)g_sa2)[sw];
    }
}
__global__ void k_gatherB() {         // grid (NKT, 16)
    __shared__ int cidx[64];
    const int tid = threadIdx.x;
    const int kt = blockIdx.x, tn = blockIdx.y;
    if (tid < 64) cidx[tid] = g_topidx[tn * 64 + tid];
    __syncthreads();
    size_t wb = (size_t)(tn * NKT + kt) * 2048;
    for (int w = tid; w < 2048; w += 256) {
        int nloc, k16, kp;
        b_inv<64>(w, nloc, k16, kp);
        int ci = cidx[nloc];
        size_t sw = (size_t)((ci >> 7) * NKT + kt) * 4096 + a_word(ci & 127, k16, kp);
        ((uint32_t*)g_taB0)[wb + w] = ((const uint32_t*)g_sa0)[sw];
        ((uint32_t*)g_taB1)[wb + w] = ((const uint32_t*)g_sa1)[sw];
        ((uint32_t*)g_taB2)[wb + w] = ((const uint32_t*)g_sa2)[sw];
    }
}
__global__ void k_topmeta(float* __restrict__ out_topidx) {
    int t = threadIdx.x;
    int ci = g_topidx[t];
    g_topm[t] = g_mention[ci];
    out_topidx[t] = (float)ci;
}

// ---------------- bf16 MMA ----------------------------------------
__device__ __forceinline__ void mma_bf16(float c[4], const uint4& a, const uint2& b) {
    asm volatile(
        "mma.sync.aligned.m16n8k16.row.col.f32.bf16.bf16.f32 "
        "{%0,%1,%2,%3}, {%4,%5,%6,%7}, {%8,%9}, {%0,%1,%2,%3};"
        : "+f"(c[0]), "+f"(c[1]), "+f"(c[2]), "+f"(c[3])
        : "r"(a.x), "r"(a.y), "r"(a.z), "r"(a.w), "r"(b.x), "r"(b.y));
}

// ---------------- GEMM3: bf16x2 3-pass, single-stage 2 CTA/SM -----
// Measured R14: tensor pipe 67%, ~210-220us. Proven best for GEMM3.
__global__ __launch_bounds__(256, 2)
void k_gemm3(const float* __restrict__ bias, float* __restrict__ C) {
    extern __shared__ char sm[];
    const int tid = threadIdx.x, lane = tid & 31, wid = tid >> 5;
    const int warp_m = wid >> 1, warp_n = wid & 1;
    const int tm = blockIdx.y, tn = blockIdx.x;
    const __nv_bfloat16* Ab[2] = {g_sa0, g_sa1};
    const __nv_bfloat16* Bb[2] = {g_wb0, g_wb1};

    float c[2][8][4];
    #pragma unroll
    for (int ma = 0; ma < 2; ++ma)
        #pragma unroll
        for (int nb = 0; nb < 8; ++nb)
            #pragma unroll
            for (int q = 0; q < 4; ++q) c[ma][nb][q] = 0.f;

    auto load_tile = [&](int kt) {
        for (int i = tid; i < 4096; i += 256) {
            int region = i >> 10, off = i & 1023;
            const char* src = (region < 2)
                ? (const char*)Ab[region] + ((size_t)(tm * NKT + kt)) * 16384 + (size_t)off * 16
                : (const char*)Bb[region - 2] + ((size_t)(tn * NKT + kt)) * 16384 + (size_t)off * 16;
            CP_ASYNC16(sm_addr(sm + region * 16384 + off * 16), src);
        }
        CP_COMMIT();
    };
    load_tile(0);

    for (int kt = 0; kt < NKT; ++kt) {
        CP_WAIT0();
        __syncthreads();
        char* bA = sm;
        char* bB = sm + 32768;
        #pragma unroll
        for (int k16 = 0; k16 < 4; ++k16) {
            uint4 a[2][2]; uint2 b[2][8];
            #pragma unroll
            for (int s = 0; s < 2; ++s)
                #pragma unroll
                for (int ma = 0; ma < 2; ++ma)
                    a[s][ma] = *(const uint4*)(bA + s * 16384 + k16 * 4096
                                               + (warp_m * 2 + ma) * 512 + lane * 16);
            #pragma unroll
            for (int s = 0; s < 2; ++s)
                #pragma unroll
                for (int nb = 0; nb < 8; ++nb)
                    b[s][nb] = *(const uint2*)(bB + s * 16384 + k16 * 4096
                                               + (warp_n * 8 + nb) * 256 + lane * 8);
            #pragma unroll
            for (int ma = 0; ma < 2; ++ma)
                #pragma unroll
                for (int nb = 0; nb < 8; ++nb) {
                    mma_bf16(c[ma][nb], a[0][ma], b[0][nb]);
                    mma_bf16(c[ma][nb], a[0][ma], b[1][nb]);
                    mma_bf16(c[ma][nb], a[1][ma], b[0][nb]);
                }
        }
        __syncthreads();
        if (kt + 1 < NKT) load_tile(kt + 1);
    }

    const int g = lane >> 2, t = lane & 3;
    const int row0 = tm * 128, col0 = tn * 128;
    #pragma unroll
    for (int ma = 0; ma < 2; ++ma) {
        int r0 = row0 + (warp_m * 2 + ma) * 16 + g;
        #pragma unroll
        for (int nb = 0; nb < 8; ++nb) {
            int cc = col0 + (warp_n * 8 + nb) * 8 + 2 * t;
            float b0 = bias[cc], b1 = bias[cc + 1];
            float v0 = fmaxf(__fadd_rn(c[ma][nb][0], b0), 0.f);
            float v1 = fmaxf(__fadd_rn(c[ma][nb][1], b1), 0.f);
            float v2 = fmaxf(__fadd_rn(c[ma][nb][2], b0), 0.f);
            float v3 = fmaxf(__fadd_rn(c[ma][nb][3], b1), 0.f);
            *(float2*)&C[(size_t)r0 * UHID + cc] = make_float2(v0, v1);
            *(float2*)&C[(size_t)(r0 + 8) * UHID + cc] = make_float2(v2, v3);
        }
    }
}

// ---------------- GEMM6: bf16x3 6-pass, double-buffered 1 CTA -----
// R17: revert to the R14 double-buffered pipeline (proven best for
// GEMM6; both 2-CTA single-stage variants regressed). One delta vs
// R14: plain per-kt fold instead of Kahan — numerically proven safe
// by R16 (rel_err 5.59e-34), saves ~13% of non-MMA instructions.
__global__ __launch_bounds__(256, 1)
void k_gemm6(const __nv_bfloat16* __restrict__ A0, const __nv_bfloat16* __restrict__ A1,
             const __nv_bfloat16* __restrict__ A2,
             const __nv_bfloat16* __restrict__ B0, const __nv_bfloat16* __restrict__ B1,
             const __nv_bfloat16* __restrict__ B2,
             const float* __restrict__ bias, float* __restrict__ C,
             int Nstore, int ldc) {
    extern __shared__ char sm[];
    const int tid = threadIdx.x, lane = tid & 31, wid = tid >> 5;
    const int warp_m = wid >> 1, warp_n = wid & 1;
    const int tm = blockIdx.y, tn = blockIdx.x;
    const __nv_bfloat16* Ab[3] = {A0, A1, A2};
    const __nv_bfloat16* Bb[3] = {B0, B1, B2};

    float acc[2][4][4];
    #pragma unroll
    for (int ma = 0; ma < 2; ++ma)
        #pragma unroll
        for (int nb = 0; nb < 4; ++nb)
            #pragma unroll
            for (int q = 0; q < 4; ++q) acc[ma][nb][q] = 0.f;

    auto load_tile = [&](int kt, int buf) {
        char* dst = sm + buf * 73728;
        for (int i = tid; i < 4608; i += 256) {
            const char* src; uint32_t doff;
            if (i < 3072) {
                int s = i >> 10, off = i & 1023;
                src = (const char*)Ab[s] + ((size_t)(tm * NKT + kt)) * 16384 + (size_t)off * 16;
                doff = s * 16384 + off * 16;
            } else {
                int j = i - 3072;
                int s = j >> 9, off = j & 511;
                src = (const char*)Bb[s] + ((size_t)(tn * NKT + kt)) * 8192 + (size_t)off * 16;
                doff = 49152 + s * 8192 + off * 16;
            }
            CP_ASYNC16(sm_addr(dst + doff), src);
        }
        CP_COMMIT();
    };
    load_tile(0, 0);
    load_tile(1, 1);

    const int pa[6] = {0, 0, 1, 1, 0, 2};
    const int pb[6] = {0, 1, 0, 1, 2, 0};

    for (int kt = 0; kt < NKT; ++kt) {
        CP_WAIT1();
        __syncthreads();
        char* bA = sm + (kt & 1) * 73728;
        char* bB = bA + 49152;
        float loc[2][4][4];
        #pragma unroll
        for (int ma = 0; ma < 2; ++ma)
            #pragma unroll
            for (int nb = 0; nb < 4; ++nb)
                #pragma unroll
                for (int q = 0; q < 4; ++q) loc[ma][nb][q] = 0.f;
        #pragma unroll
        for (int k16 = 0; k16 < 4; ++k16) {
            uint4 a[3][2]; uint2 b[3][4];
            #pragma unroll
            for (int s = 0; s < 3; ++s)
                #pragma unroll
                for (int ma = 0; ma < 2; ++ma)
                    a[s][ma] = *(const uint4*)(bA + s * 16384 + k16 * 4096
                                               + (warp_m * 2 + ma) * 512 + lane * 16);
            #pragma unroll
            for (int s = 0; s < 3; ++s)
                #pragma unroll
                for (int nb = 0; nb < 4; ++nb)
                    b[s][nb] = *(const uint2*)(bB + s * 8192 + k16 * 2048
                                               + (warp_n * 4 + nb) * 256 + lane * 8);
            #pragma unroll
            for (int pr = 0; pr < 6; ++pr)
                #pragma unroll
                for (int ma = 0; ma < 2; ++ma)
                    #pragma unroll
                    for (int nb = 0; nb < 4; ++nb)
                        mma_bf16(loc[ma][nb], a[pa[pr]][ma], b[pb[pr]][nb]);
        }
        // plain fold of k64 partial into master (R16-proven numerics)
        #pragma unroll
        for (int ma = 0; ma < 2; ++ma)
            #pragma unroll
            for (int nb = 0; nb < 4; ++nb)
                #pragma unroll
                for (int q = 0; q < 4; ++q)
                    acc[ma][nb][q] = __fadd_rn(acc[ma][nb][q], loc[ma][nb][q]);
        __syncthreads();
        if (kt + 2 < NKT) load_tile(kt + 2, kt & 1);
        else CP_COMMIT();
    }

    const int g = lane >> 2, t = lane & 3;
    const int row0 = tm * 128, col0 = tn * 64;
    #pragma unroll
    for (int ma = 0; ma < 2; ++ma) {
        int r0 = row0 + (warp_m * 2 + ma) * 16 + g;
        #pragma unroll
        for (int nb = 0; nb < 4; ++nb) {
            int cc = col0 + (warp_n * 4 + nb) * 8 + 2 * t;
            if (cc >= Nstore) continue;
            float v0 = acc[ma][nb][0], v1 = acc[ma][nb][1];
            float v2 = acc[ma][nb][2], v3 = acc[ma][nb][3];
            if (bias) {
                float b0 = bias[cc];
                float b1 = (cc + 1 < Nstore) ? bias[cc + 1] : 0.f;
                v0 = __fadd_rn(v0, b0); v1 = __fadd_rn(v1, b1);
                v2 = __fadd_rn(v2, b0); v3 = __fadd_rn(v3, b1);
            }
            if (cc + 1 < Nstore) {
                *(float2*)&C[(size_t)r0 * ldc + cc] = make_float2(v0, v1);
                *(float2*)&C[(size_t)(r0 + 8) * ldc + cc] = make_float2(v2, v3);
            } else {
                C[(size_t)r0 * ldc + cc] = v0;
                C[(size_t)(r0 + 8) * ldc + cc] = v2;
            }
        }
    }
}

// ---------------- mention score -----------------------------------
__global__ void k_score(const float* __restrict__ w_u2,
                        const float* __restrict__ b_u2) {
    int warp = (blockIdx.x * blockDim.x + threadIdx.x) >> 5;
    int lane = threadIdx.x & 31;
    if (warp >= C_SP) return;
    const float* row = g_hid1 + (size_t)warp * UHID;
    double acc = 0.0;
    #pragma unroll 8
    for (int i = lane; i < UHID; i += 32) acc += (double)row[i] * (double)w_u2[i];
    #pragma unroll
    for (int o = 16; o; o >>= 1) acc += __shfl_xor_sync(0xffffffffu, acc, o);
    if (lane == 0) g_mention[warp] = (float)(acc + (double)b_u2[0]);
}

// ---------------- sort + greedy + compact -------------------------
__device__ __forceinline__ bool sort_before(float xk, int xi, float yk, int yi) {
    return (xk > yk) || (xk == yk && xi < yi);
}

__global__ void k_extract(const int* __restrict__ starts,
                          const int* __restrict__ widths) {
    extern __shared__ int sh[];
    float* key = (float*)sh;
    int* idx = sh + 4096;
    int* es  = sh + 8192;
    int* flg = sh + 12288;
    const int tid = threadIdx.x;       // 1024 threads
    const int ln32 = tid & 31, wrp = tid >> 5;
    const int ebase = wrp * 128 + ln32 * 4;

    for (int i = tid; i < C_SP; i += 1024) flg[i] = 0;

    float kq[4]; int iq[4];
    #pragma unroll
    for (int q = 0; q < 4; ++q) { kq[q] = g_mention[ebase + q]; iq[q] = ebase + q; }

    auto reg_phase = [&](unsigned k, unsigned j) {
        if (j >= 4) {
            unsigned lm = j >> 2;
            #pragma unroll
            for (int q = 0; q < 4; ++q) {
                float pk = __shfl_xor_sync(0xffffffffu, kq[q], lm);
                int   pi = __shfl_xor_sync(0xffffffffu, iq[q], lm);
                int e = ebase + q;
                int i = e & ~(int)j;
                bool dir = ((i & (int)k) == 0);
                bool swp;
                if ((e & (int)j) == 0)
                    swp = (sort_before(pk, pi, kq[q], iq[q]) == dir);
                else
                    swp = (sort_before(kq[q], iq[q], pk, pi) == dir);
                if (swp) { kq[q] = pk; iq[q] = pi; }
            }
        } else if (j == 2) {
            #pragma unroll
            for (int q = 0; q < 2; ++q) {
                int i = ebase + q;
                bool dir = ((i & (int)k) == 0);
                if (sort_before(kq[q + 2], iq[q + 2], kq[q], iq[q]) == dir) {
                    float tk = kq[q]; int ti = iq[q];
                    kq[q] = kq[q + 2]; iq[q] = iq[q + 2];
                    kq[q + 2] = tk; iq[q + 2] = ti;
                }
            }
        } else {
            #pragma unroll
            for (int q = 0; q < 4; q += 2) {
                int i = ebase + q;
                bool dir = ((i & (int)k) == 0);
                if (sort_before(kq[q + 1], iq[q + 1], kq[q], iq[q]) == dir) {
                    float tk = kq[q]; int ti = iq[q];
                    kq[q] = kq[q + 1]; iq[q] = iq[q + 1];
                    kq[q + 1] = tk; iq[q + 1] = ti;
                }
            }
        }
    };

    for (unsigned k = 2; k <= 128; k <<= 1)
        for (unsigned j = k >> 1; j > 0; j >>= 1) reg_phase(k, j);
    #pragma unroll
    for (int q = 0; q < 4; ++q) { key[ebase + q] = kq[q]; idx[ebase + q] = iq[q]; }
    __syncthreads();

    for (unsigned k = 256; k <= 4096; k <<= 1) {
        for (unsigned j = k >> 1; j >= 128; j >>= 1) {
            for (unsigned t = tid; t < 2048; t += 1024) {
                unsigned i = ((t & ~(j - 1)) << 1) | (t & (j - 1));
                unsigned l = i | j;
                float ki = key[i], kl = key[l];
                int   ii = idx[i], il = idx[l];
                bool before_l_i = (kl > ki) || (kl == ki && il < ii);
                bool dir = ((i & k) == 0);
                if (before_l_i == dir) {
                    key[i] = kl; key[l] = ki;
                    idx[i] = il; idx[l] = ii;
                }
            }
            __syncthreads();
        }
        #pragma unroll
        for (int q = 0; q < 4; ++q) { kq[q] = key[ebase + q]; iq[q] = idx[ebase + q]; }
        for (unsigned j = 64; j > 0; j >>= 1) reg_phase(k, j);
        #pragma unroll
        for (int q = 0; q < 4; ++q) { key[ebase + q] = kq[q]; idx[ebase + q] = iq[q]; }
        __syncthreads();
    }

    volatile int* le = (volatile int*)key;
    volatile int* ves = (volatile int*)es;
    for (int i = tid; i < T_TOK; i += 1024) {
        ((int*)key)[i] = -1;
        es[i] = T_TOK;
    }
    __syncthreads();

    if (tid < 32) {
        int lane = tid;
        int count = 0;
        for (int p = 0; p < C_SP && count < M_TOP; ++p) {
            int ci = idx[p];
            int s = starts[ci];
            int w = widths[ci];
            int e = s + w;
            bool crossing = false;
            if (lane < w) {
                crossing = (le[s + 1 + lane] > e) | (ves[s + lane] < s);
            }
            unsigned m = __ballot_sync(0xffffffffu, crossing);
            if (m == 0u) {
                if (lane == 0) {
                    int cur = le[s]; if (e > cur) ((int*)key)[s] = e;
                    int cur2 = ves[e]; if (s < cur2) es[e] = s;
                    flg[ci] = 1;
                }
                count++;
            }
            __syncwarp();
        }
    }
    __syncthreads();

    __shared__ int wsum[32];
    __shared__ int woff[33];
    int base = tid * 4;
    int f0 = flg[base], f1 = flg[base + 1], f2 = flg[base + 2], f3 = flg[base + 3];
    int c = f0 + f1 + f2 + f3;
    int inc = c;
    int lane = tid & 31, wid = tid >> 5;
    #pragma unroll
    for (int o = 1; o < 32; o <<= 1) {
        int n = __shfl_up_sync(0xffffffffu, inc, o);
        if (lane >= o) inc += n;
    }
    if (lane == 31) wsum[wid] = inc;
    __syncthreads();
    if (tid == 0) {
        int run = 0;
        for (int i = 0; i < 32; ++i) { woff[i] = run; run += wsum[i]; }
        woff[32] = run;
    }
    __syncthreads();
    int pos = woff[wid] + (inc - c);
    if (f0) { if (pos < M_TOP) g_topidx[pos] = base;     pos++; }
    if (f1) { if (pos < M_TOP) g_topidx[pos] = base + 1; pos++; }
    if (f2) { if (pos < M_TOP) g_topidx[pos] = base + 2; pos++; }
    if (f3) { if (pos < M_TOP) g_topidx[pos] = base + 3; pos++; }
    int total = woff[32];
    for (int p = total + tid; p < M_TOP; p += 1024) g_topidx[p] = C_SP - 1;
}

// ---------------- fast scores + per-row top-50 --------------------
__global__ void k_topk(float* __restrict__ out_ant,
                       float* __restrict__ out_mask,
                       float* __restrict__ out_score) {
    __shared__ float v[M_TOP];
    __shared__ float wv[8];
    __shared__ int   wi[8];
    const int i = blockIdx.x;
    const int tid = threadIdx.x;
    const int lane = tid & 31, wid = tid >> 5;
    const float mi = g_topm[i];
    for (int j = tid; j < M_TOP; j += 256) {
        float val = __fadd_rn(__fadd_rn(__fadd_rn(mi, g_topm[j]),
                                        (j < i) ? 0.f : NEGV),
                              g_fast[(size_t)i * M_TOP + j]);
        v[j] = val;
    }
    __syncthreads();
    for (int k = 0; k < K_ANT; ++k) {
        float bv = -INFINITY; int bi = M_TOP;
        for (int j = tid; j < M_TOP; j += 256) {
            float x = v[j];
            if (x > bv || (x == bv && j < bi)) { bv = x; bi = j; }
        }
        #pragma unroll
        for (int o = 16; o; o >>= 1) {
            float ok = __shfl_xor_sync(0xffffffffu, bv, o);
            int   oi = __shfl_xor_sync(0xffffffffu, bi, o);
            if (ok > bv || (ok == bv && oi < bi)) { bv = ok; bi = oi; }
        }
        if (lane == 0) { wv[wid] = bv; wi[wid] = bi; }
        __syncthreads();
        if (tid == 0) {
            float fv = wv[0]; int fi = wi[0];
            #pragma unroll
            for (int w = 1; w < 8; ++w)
                if (wv[w] > fv || (wv[w] == fv && wi[w] < fi)) { fv = wv[w]; fi = wi[w]; }
            out_ant[(size_t)i * K_ANT + k]   = (float)fi;
            out_mask[(size_t)i * K_ANT + k]  = (fi < i) ? 1.f : 0.f;
            out_score[(size_t)i * K_ANT + k] = fv;
            v[fi] = -INFINITY;
        }
        __syncthreads();
    }
}

// ---------------- launch ------------------------------------------
extern "C" void kernel_launch(void* const* d_in, const int* in_sizes, int n_in,
                              void* d_out, int out_size) {
    const float* hs      = (const float*)d_in[0];
    const int*   starts  = (const int*)d_in[1];
    const int*   widths  = (const int*)d_in[2];
    int base = 3;
    if (n_in >= 14 && in_sizes[3] == 1 && in_sizes[4] == 1) base = 5;
    const float* w_width = (const float*)d_in[base + 0];
    const float* w_attn  = (const float*)d_in[base + 1];
    const float* b_attn  = (const float*)d_in[base + 2];
    const float* w_u1    = (const float*)d_in[base + 3];
    const float* b_u1    = (const float*)d_in[base + 4];
    const float* w_u2    = (const float*)d_in[base + 5];
    const float* b_u2    = (const float*)d_in[base + 6];
    const float* w_fast  = (const float*)d_in[base + 7];
    const float* b_fast  = (const float*)d_in[base + 8];

    float* out = (float*)d_out;
    float* out_topidx = out;
    float* out_ant    = out + M_TOP;
    float* out_mask   = out + M_TOP + M_TOP * K_ANT;
    float* out_score  = out + M_TOP + 2 * M_TOP * K_ANT;

    float *p_span, *p_hid1, *p_tmp, *p_fast;
    __nv_bfloat16 *p_sa0, *p_sa1, *p_sa2;
    __nv_bfloat16 *p_fb0, *p_fb1, *p_fb2;
    __nv_bfloat16 *p_ta0, *p_ta1, *p_ta2, *p_taB0, *p_taB1, *p_taB2;
    __nv_bfloat16 *p_tb0, *p_tb1, *p_tb2;
    cudaGetSymbolAddress((void**)&p_span, g_span_emb);
    cudaGetSymbolAddress((void**)&p_hid1, g_hid1);
    cudaGetSymbolAddress((void**)&p_tmp,  g_tmp);
    cudaGetSymbolAddress((void**)&p_fast, g_fast);
    cudaGetSymbolAddress((void**)&p_sa0, g_sa0);
    cudaGetSymbolAddress((void**)&p_sa1, g_sa1);
    cudaGetSymbolAddress((void**)&p_sa2, g_sa2);
    cudaGetSymbolAddress((void**)&p_fb0, g_fbx0);
    cudaGetSymbolAddress((void**)&p_fb1, g_fbx1);
    cudaGetSymbolAddress((void**)&p_fb2, g_fbx2);
    cudaGetSymbolAddress((void**)&p_ta0, g_ta0);
    cudaGetSymbolAddress((void**)&p_ta1, g_ta1);
    cudaGetSymbolAddress((void**)&p_ta2, g_ta2);
    cudaGetSymbolAddress((void**)&p_taB0, g_taB0);
    cudaGetSymbolAddress((void**)&p_taB1, g_taB1);
    cudaGetSymbolAddress((void**)&p_taB2, g_taB2);
    cudaGetSymbolAddress((void**)&p_tb0, g_tb0);
    cudaGetSymbolAddress((void**)&p_tb1, g_tb1);
    cudaGetSymbolAddress((void**)&p_tb2, g_tb2);

    cudaFuncSetAttribute(k_gemm3, cudaFuncAttributeMaxDynamicSharedMemorySize, 65536);
    cudaFuncSetAttribute(k_gemm6, cudaFuncAttributeMaxDynamicSharedMemorySize, 147456);
    cudaFuncSetAttribute(k_extract, cudaFuncAttributeMaxDynamicSharedMemorySize, 65536);

    const int smPre  = 64 * 132 * 4;     // k_pre split part
    const int smA    = 128 * 68 * 4;     // k_splitA_frag
    const int smB64  = 64 * 68 * 4;      // k_splitB64

    // #0: fused token_logits + w_u1 split
    k_pre<<<512 + NKT * 8, 256, smPre>>>(hs, w_attn, b_attn, w_u1);
    // #1: span embeddings
    k_span_emb<<<C_SP, 256>>>(hs, starts, widths, w_width);
    // #2: span_emb -> A-frag splits
    { dim3 g(NKT, C_SP / 128);
      k_splitA_frag<<<g, 256, smA>>>(p_span, p_sa0, p_sa1, p_sa2); }
    // #3: GEMM3 (ncu capture target)
    { dim3 g(UHID / 128, C_SP / 128);
      k_gemm3<<<g, 256, 65536>>>(b_u1, p_hid1); }
    // w_fast split (needed only by GEMM7)
    { dim3 g(NKT, NKT); k_splitB64<<<g, 256, smB64>>>(w_fast); }
    k_score<<<C_SP * 32 / 256, 256>>>(w_u2, b_u2);
    k_extract<<<1, 1024, 65536>>>(starts, widths);
    k_topmeta<<<1, 1024>>>(out_topidx);
    { dim3 g(NKT, 8);  k_gatherA<<<g, 256>>>(); }
    { dim3 g(NKT, 16); k_gatherB<<<g, 256>>>(); }
    { dim3 g(NKT, M_TOP / 128);
      k_gemm6<<<g, 256, 147456>>>(p_ta0, p_ta1, p_ta2, p_fb0, p_fb1, p_fb2,
                                  b_fast, p_tmp, SPAND, SPAND); }
    { dim3 g(NKT, M_TOP / 128);
      k_splitA_frag<<<g, 256, smA>>>(p_tmp, p_tb0, p_tb1, p_tb2); }
    { dim3 g(M_TOP / 64, M_TOP / 128);
      k_gemm6<<<g, 256, 147456>>>(p_tb0, p_tb1, p_tb2, p_taB0, p_taB1, p_taB2,
                                  nullptr, p_fast, M_TOP, M_TOP); }
    k_topk<<<M_TOP, 256>>>(out_ant, out_mask, out_score);

    (void)in_sizes; (void)n_in; (void)out_size;
}